// round 11
// baseline (speedup 1.0000x reference)
#include <cuda_runtime.h>
#include <math_constants.h>
#include <float.h>

#define BB 8
#define QQ 2048
#define GG 128
#define CC 512

#define TLSA 256              // solver threads per block
#define NW   (TLSA / 32)      // warps
#define KC   (QQ / TLSA)      // 8 contiguous columns per thread

// Transposed cost scratch: costT[b][g][q], fp32 (identical bits to final_cost)
__device__ float g_costT[BB * GG * QQ];

// ---------------------------------------------------------------------------
// Kernel 1: fused cost computation + transpose (bit-exact vs reference).
// ---------------------------------------------------------------------------
__global__ __launch_bounds__(256) void cost_kernel(
    const float* __restrict__ prob,     // [B][Q][C]
    const float* __restrict__ center,   // [B][Q][G]
    const float* __restrict__ size_,    // [B][Q][G]
    const float* __restrict__ gious,    // [B][Q][G]
    const void*  __restrict__ labels_v, // [B][G] int32 (default) or int64
    int labels_i64,
    float* __restrict__ fc)             // [B][Q][G]  (output region)
{
    __shared__ float tile[32][33];
    const int b  = blockIdx.z;
    const int g0 = blockIdx.x * 32;
    const int q0 = blockIdx.y * 32;
    const int tx = threadIdx.x;
    const int ty = threadIdx.y;

    const int g = g0 + tx;
    int cls;
    if (labels_i64) cls = (int)((const long long*)labels_v)[b * GG + g];
    else            cls = ((const int*)labels_v)[b * GG + g];

#pragma unroll
    for (int r = 0; r < 4; ++r) {
        const int q = q0 + ty + r * 8;
        const size_t bq = (size_t)b * QQ + q;
        const float x = prob[bq * CC + cls];

        const float p = __fdiv_rn(1.0f, __fadd_rn(1.0f, expf(-x)));

        const float t0  = __fsub_rn(p, 1e-8f);
        const float neg = __fmul_rn(__fmul_rn(0.75f, __fmul_rn(p, p)),
                                    -log1pf(-t0));
        const float omp = __fsub_rn(1.0f, p);
        const float pos = __fmul_rn(__fmul_rn(0.25f, __fmul_rn(omp, omp)),
                                    -logf(__fadd_rn(p, 1e-8f)));
        const float diff = __fsub_rn(pos, neg);

        const size_t idx = bq * GG + g;
        float cost = __fmul_rn(2.0f, diff);
        cost = __fadd_rn(cost, __fmul_rn(5.0f, center[idx]));
        cost = __fadd_rn(cost, __fmul_rn(1.0f, size_[idx]));
        cost = __fadd_rn(cost, __fmul_rn(2.0f, -gious[idx]));

        fc[idx] = cost;
        tile[ty + r * 8][tx] = cost;
    }
    __syncthreads();

#pragma unroll
    for (int r = 0; r < 4; ++r) {
        const int gl = ty + r * 8;
        g_costT[((size_t)b * GG + (g0 + gl)) * QQ + (q0 + tx)] = tile[tx][gl];
    }
}

// ordered-float encode/decode (monotonic u32)
__device__ __forceinline__ unsigned ford(float x) {
    unsigned b = __float_as_uint(x);
    return b ^ ((b & 0x80000000u) ? 0xFFFFFFFFu : 0x80000000u);
}
__device__ __forceinline__ float funord(unsigned k) {
    unsigned b = (k & 0x80000000u) ? (k ^ 0x80000000u) : ~k;
    return __uint_as_float(b);
}

// ---------------------------------------------------------------------------
// Kernel 2: reference degenerate JV. Single barrier per chain iteration:
//  - per-warp reduce via redux.sync.min.u32 on ordered-fp32 keys, ballot
//    picks lowest attaining lane (= smallest column, contiguous ownership)
//  - (min, second-min) pair per warp -> every thread computes the global
//    min, winner column, and ambiguity after ONE __syncthreads
//  - owner thread accumulates the exact fp64 chain sum S in shared s_S
//    (no delta broadcast); tau-ambiguous iterations take the exact
//    full-fp64 reduce. Selection bit-identical to a pure fp64 scan.
//  tau = 1.2e-7*(100 + 2.5*UVmax): sound bound 2*eps32*(Cmax + 2*Vmax)
//  with Cmax<=100 (5x margin) and Vmax<=UVmax (25% margin on UV term).
// ---------------------------------------------------------------------------
__global__ __launch_bounds__(TLSA, 1) void lsa_kernel(
    const void* __restrict__ nactual_v,
    int n_i64,
    float* __restrict__ out_inds_f32,
    long long* __restrict__ out_inds_i64,
    float* __restrict__ out_mask)
{
    __shared__ double u[GG + 1];
    __shared__ short  p[QQ + 1];
    __shared__ unsigned long long slots[2][NW];
    __shared__ unsigned m2s[2][NW];
    __shared__ double s_S;
    __shared__ double sv[NW];
    __shared__ int    si[NW];
    __shared__ short  ccols[GG + 4];
    __shared__ double cA[GG + 4];

    const int b = blockIdx.x;
    const int t = threadIdx.x;
    int n;
    if (n_i64) n = (int)((const long long*)nactual_v)[b];
    else       n = ((const int*)nactual_v)[b];
    if (n < 0) n = 0;
    if (n > GG) n = GG;

    const float* Cb = g_costT + (size_t)b * GG * QQ;
    const int base = t * KC;            // owns columns base+1 .. base+KC

    double v64[KC];
    float  v32[KC];
#pragma unroll
    for (int k = 0; k < KC; ++k) { v64[k] = 0.0; v32[k] = 0.0f; }

    for (int j = t; j <= QQ; j += TLSA) p[j] = 0;
    for (int i = t; i <= GG; i += TLSA) u[i] = 0.0;
    if (t == 0) s_S = 0.0;
    __syncthreads();

    double UVmax = 0.0;
    int par = 0;
    const unsigned fm = 0xffffffffu;
    const int lane = t & 31;
    const int wix  = t >> 5;

    for (int i = 1; i <= n; ++i) {
        unsigned mask = (1u << KC) - 1u;
        int    i0 = i;
        int    len = 0;
        int    jsel = 0;
        const float tau = (float)(1.2e-7 * (100.0 + 2.5 * UVmax));

        const float* row0 = Cb + (size_t)(i0 - 1) * QQ + base;
        float4 r0 = *(const float4*)(row0);
        float4 r1 = *(const float4*)(row0 + 4);

        while (true) {
            const double ui0 = u[i0];
            const float c32[KC] = { r0.x, r0.y, r0.z, r0.w, r1.x, r1.y, r1.z, r1.w };

            // local (min, second-min) over my free columns, ordered-uint keys
            unsigned key1 = 0xFFFFFFFFu, key2 = 0xFFFFFFFFu;
            int k1 = 0;
#pragma unroll
            for (int k = 0; k < KC; ++k) {
                const float w = __fsub_rn(c32[k], v32[k]);
                unsigned kk = ford(w);
                if (!((mask >> k) & 1)) kk = 0xFFFFFFFFu;
                if (kk < key1) { key2 = key1; key1 = kk; k1 = k; }
                else if (kk < key2) { key2 = kk; }
            }

            // warp reduce via redux: min, owner lane, second-min, winner col
            const unsigned m1 = __reduce_min_sync(fm, key1);
            const unsigned ball = __ballot_sync(fm, key1 == m1);
            const int owner_lane = __ffs(ball) - 1;
            const unsigned cand2 = (lane == owner_lane) ? key2 : key1;
            const unsigned m2 = __reduce_min_sync(fm, cand2);
            const int col1 = __shfl_sync(fm, base + k1 + 1, owner_lane);

            if (lane == 0) {
                slots[par][wix] = ((unsigned long long)m1 << 32) | (unsigned)col1;
                m2s[par][wix] = m2;
            }
            __syncthreads();                       // the single barrier

            // slot tree: global min + global second-min key
            unsigned long long a0 = slots[par][0];
#pragma unroll
            for (int wi = 1; wi < NW; ++wi) {
                const unsigned long long x = slots[par][wi];
                if (x < a0) a0 = x;
            }
            unsigned gsec = 0xFFFFFFFFu;
#pragma unroll
            for (int wi = 0; wi < NW; ++wi) {
                const unsigned long long x = slots[par][wi];
                const unsigned cnd = (x == a0) ? m2s[par][wi] : (unsigned)(x >> 32);
                if (cnd < gsec) gsec = cnd;
            }
            par ^= 1;

            const float gw = funord((unsigned)(a0 >> 32));
            const float gs = funord(gsec);                    // NaN if none
            const bool ambig = (gs <= __fadd_rn(gw, tau));    // NaN -> false

            int jj;
            double delta_fb = 0.0;
            bool fb = false;
            if (!ambig) {
                jj = (int)(a0 & 0xffffffffu);
            } else {
                // exact full fp64 reduce (uniform branch)
                double best = DBL_MAX; int bestj = 1 << 30;
#pragma unroll
                for (int k = 0; k < KC; ++k) {
                    if ((mask >> k) & 1) {
                        const double cur = ((double)c32[k] - ui0) - v64[k];
                        if (cur < best) { best = cur; bestj = base + k + 1; }
                    }
                }
#pragma unroll
                for (int off = 16; off; off >>= 1) {
                    const double ov = __shfl_down_sync(fm, best, off);
                    const int    oi = __shfl_down_sync(fm, bestj, off);
                    if (ov < best || (ov == best && oi < bestj)) { best = ov; bestj = oi; }
                }
                if (lane == 0) { sv[wix] = best; si[wix] = bestj; }
                __syncthreads();
                double dd = sv[0]; int jjj = si[0];
#pragma unroll
                for (int wi = 1; wi < NW; ++wi) {
                    if (sv[wi] < dd || (sv[wi] == dd && si[wi] < jjj)) { dd = sv[wi]; jjj = si[wi]; }
                }
                __syncthreads();                   // protect sv/si reuse
                jj = jjj; delta_fb = dd; fb = true;
            }

            const int pj = p[jj];

            // prefetch next chain row as early as possible
            if (pj != 0) {
                const float* nr = Cb + (size_t)(pj - 1) * QQ + base;
                r0 = *(const float4*)(nr);
                r1 = *(const float4*)(nr + 4);
            }

            // chain-sum bookkeeping: owner thread (fast) / t0 (fallback)
            if (!fb) {
                if (((jj - 1) >> 3) == t) {
                    const int kk2 = (jj - 1) & (KC - 1);
                    const double delta = ((double)c32[kk2] - ui0) - v64[kk2];
                    const double Snew = s_S + delta;
                    if (pj != 0) { ccols[len] = (short)jj; cA[len] = Snew; }
                    s_S = Snew;
                }
            } else if (t == 0) {
                const double Snew = s_S + delta_fb;
                if (pj != 0) { ccols[len] = (short)jj; cA[len] = Snew; }
                s_S = Snew;
            }

            if (((jj - 1) >> 3) == t)
                mask &= ~(1u << ((jj - 1) & (KC - 1)));

            if (pj == 0) { jsel = jj; break; }
            ++len;
            i0 = pj;
        }

        // ---- row end: apply deferred potential updates ----
        __syncthreads();
        const double S = s_S;
        if (t == 0) { u[i] += S; p[jsel] = (short)i; }
        if (t < len) { u[p[ccols[t]]] += S - cA[t]; }

        double bump = fabs(S);
        for (int c = 0; c < len; ++c) {
            const int    jc  = ccols[c];
            const double adj = S - cA[c];
            bump = fmax(bump, fabs(adj));
            const int rel = jc - 1 - base;
            if (rel >= 0 && rel < KC) {
#pragma unroll
                for (int k = 0; k < KC; ++k)
                    if (rel == k) { v64[k] -= adj; v32[k] = (float)v64[k]; }
            }
        }
        UVmax += bump;
        __syncthreads();
        if (t == 0) s_S = 0.0;
    }

    // Emit per-proposal gt index + matched mask
    for (int j = t + 1; j <= QQ; j += TLSA) {
        const int    r = p[j];
        const size_t o = (size_t)b * QQ + (j - 1);
        if (out_inds_f32) out_inds_f32[o] = (r > 0) ? (float)(r - 1) : 0.0f;
        if (out_inds_i64) out_inds_i64[o] = (r > 0) ? (long long)(r - 1) : 0LL;
        out_mask[o] = (r > 0) ? 1.0f : 0.0f;
    }
}

// ---------------------------------------------------------------------------
extern "C" void kernel_launch(void* const* d_in, const int* in_sizes, int n_in,
                              void* d_out, int out_size) {
    const float* prob    = (const float*)d_in[0];
    const float* center  = (const float*)d_in[1];
    const float* size_   = (const float*)d_in[2];
    const float* gious   = (const float*)d_in[3];
    const void*  labels  = d_in[4];
    const void*  nactual = d_in[5];

    float*     out_f32  = (float*)d_out;
    float*     inds_f32 = nullptr;
    long long* inds_i64 = nullptr;
    float*     mask;
    float*     fc;
    int i64_world = 0;

    if (out_size == 2146304) {
        i64_world = 1;
        inds_i64 = (long long*)d_out;
        mask = out_f32 + 32768;
        fc   = out_f32 + 49152;
    } else {
        inds_f32 = out_f32;
        mask = out_f32 + BB * QQ;
        fc   = out_f32 + 2 * BB * QQ;
    }

    dim3 cgrid(GG / 32, QQ / 32, BB);
    dim3 cblk(32, 8);
    cost_kernel<<<cgrid, cblk>>>(prob, center, size_, gious, labels, i64_world, fc);

    lsa_kernel<<<BB, TLSA>>>(nactual, i64_world, inds_f32, inds_i64, mask);
}

// round 13
// speedup vs baseline: 1.5418x; 1.5418x over previous
#include <cuda_runtime.h>
#include <math_constants.h>
#include <float.h>

#define BB 8
#define QQ 2048
#define GG 128
#define CC 512

#define TLSA 256              // solver threads per block
#define NW   (TLSA / 32)      // warps
#define KC   (QQ / TLSA)      // 8 contiguous columns per thread

// Transposed cost scratch: costT[b][g][q], fp32 (identical bits to final_cost)
__device__ float g_costT[BB * GG * QQ];

// ---------------------------------------------------------------------------
// Kernel 1: fused cost computation + transpose (bit-exact vs reference).
// ---------------------------------------------------------------------------
__global__ __launch_bounds__(256) void cost_kernel(
    const float* __restrict__ prob,     // [B][Q][C]
    const float* __restrict__ center,   // [B][Q][G]
    const float* __restrict__ size_,    // [B][Q][G]
    const float* __restrict__ gious,    // [B][Q][G]
    const void*  __restrict__ labels_v, // [B][G] int32 (default) or int64
    int labels_i64,
    float* __restrict__ fc)             // [B][Q][G]  (output region)
{
    __shared__ float tile[32][33];
    const int b  = blockIdx.z;
    const int g0 = blockIdx.x * 32;
    const int q0 = blockIdx.y * 32;
    const int tx = threadIdx.x;
    const int ty = threadIdx.y;

    const int g = g0 + tx;
    int cls;
    if (labels_i64) cls = (int)((const long long*)labels_v)[b * GG + g];
    else            cls = ((const int*)labels_v)[b * GG + g];

#pragma unroll
    for (int r = 0; r < 4; ++r) {
        const int q = q0 + ty + r * 8;
        const size_t bq = (size_t)b * QQ + q;
        const float x = prob[bq * CC + cls];

        const float p = __fdiv_rn(1.0f, __fadd_rn(1.0f, expf(-x)));

        const float t0  = __fsub_rn(p, 1e-8f);
        const float neg = __fmul_rn(__fmul_rn(0.75f, __fmul_rn(p, p)),
                                    -log1pf(-t0));
        const float omp = __fsub_rn(1.0f, p);
        const float pos = __fmul_rn(__fmul_rn(0.25f, __fmul_rn(omp, omp)),
                                    -logf(__fadd_rn(p, 1e-8f)));
        const float diff = __fsub_rn(pos, neg);

        const size_t idx = bq * GG + g;
        float cost = __fmul_rn(2.0f, diff);
        cost = __fadd_rn(cost, __fmul_rn(5.0f, center[idx]));
        cost = __fadd_rn(cost, __fmul_rn(1.0f, size_[idx]));
        cost = __fadd_rn(cost, __fmul_rn(2.0f, -gious[idx]));

        fc[idx] = cost;
        tile[ty + r * 8][tx] = cost;
    }
    __syncthreads();

#pragma unroll
    for (int r = 0; r < 4; ++r) {
        const int gl = ty + r * 8;
        g_costT[((size_t)b * GG + (g0 + gl)) * QQ + (q0 + tx)] = tile[tx][gl];
    }
}

// ordered-float encode/decode (monotonic u32)
__device__ __forceinline__ unsigned ford(float x) {
    unsigned b = __float_as_uint(x);
    return b ^ ((b & 0x80000000u) ? 0xFFFFFFFFu : 0x80000000u);
}
__device__ __forceinline__ float funord(unsigned k) {
    unsigned b = (k & 0x80000000u) ? (k ^ 0x80000000u) : ~k;
    return __uint_as_float(b);
}
// ordered-double encode/decode (monotonic u64)
__device__ __forceinline__ unsigned long long dord(double x) {
    unsigned long long b = (unsigned long long)__double_as_longlong(x);
    return b ^ ((b >> 63) ? 0xFFFFFFFFFFFFFFFFull : 0x8000000000000000ull);
}
__device__ __forceinline__ double dunord(unsigned long long k) {
    unsigned long long b = (k >> 63) ? (k ^ 0x8000000000000000ull) : ~k;
    return __longlong_as_double((long long)b);
}

// ---------------------------------------------------------------------------
// Kernel 2: reference degenerate JV. Fast path identical to the proven R8
// version (redux.min + ballot per warp, one barrier, slot tree, s_S owner
// accumulation, tau window with 6.0 coefficient). NEW: the tau-ambiguous
// fallback no longer runs a full fp64 scan + 15-shfl reduce; instead each
// thread evaluates exact fp64 only for its in-window candidates (typically
// 0-2 block-wide) and the global exact min is taken via shared atomicMin on
// an ordered-double cell, then smallest column among exact ties via int
// atomicMin. Selection + delta remain bit-identical to a pure fp64 scan.
// ---------------------------------------------------------------------------
__global__ __launch_bounds__(TLSA, 1) void lsa_kernel(
    const void* __restrict__ nactual_v,
    int n_i64,
    float* __restrict__ out_inds_f32,
    long long* __restrict__ out_inds_i64,
    float* __restrict__ out_mask)
{
    __shared__ double u[GG + 1];
    __shared__ short  p[QQ + 1];
    __shared__ unsigned long long slots[2][NW];
    __shared__ unsigned m2s[2][NW];
    __shared__ double s_S;
    __shared__ unsigned long long fval[2];
    __shared__ int    fcol[2];
    __shared__ short  ccols[GG + 4];
    __shared__ double cA[GG + 4];

    const int b = blockIdx.x;
    const int t = threadIdx.x;
    int n;
    if (n_i64) n = (int)((const long long*)nactual_v)[b];
    else       n = ((const int*)nactual_v)[b];
    if (n < 0) n = 0;
    if (n > GG) n = GG;

    const float* Cb = g_costT + (size_t)b * GG * QQ;
    const int base = t * KC;            // owns columns base+1 .. base+KC

    double v64[KC];
    float  v32[KC];
#pragma unroll
    for (int k = 0; k < KC; ++k) { v64[k] = 0.0; v32[k] = 0.0f; }

    for (int j = t; j <= QQ; j += TLSA) p[j] = 0;
    for (int i = t; i <= GG; i += TLSA) u[i] = 0.0;
    if (t == 0) {
        s_S = 0.0;
        fval[0] = fval[1] = 0xFFFFFFFFFFFFFFFFull;
        fcol[0] = fcol[1] = 0x7FFFFFFF;
    }
    __syncthreads();

    double UVmax = 0.0;
    int par = 0;
    int fcnt = 0;                        // fallback sequence counter (uniform)
    const unsigned fm = 0xffffffffu;
    const int lane = t & 31;
    const int wix  = t >> 5;

    for (int i = 1; i <= n; ++i) {
        unsigned mask = (1u << KC) - 1u;
        int    i0 = i;
        int    len = 0;
        int    jsel = 0;
        const float tau = (float)(1.2e-7 * (100.0 + 6.0 * UVmax));

        const float* row0 = Cb + (size_t)(i0 - 1) * QQ + base;
        float4 r0 = *(const float4*)(row0);
        float4 r1 = *(const float4*)(row0 + 4);

        while (true) {
            const double ui0 = u[i0];
            const float c32[KC] = { r0.x, r0.y, r0.z, r0.w, r1.x, r1.y, r1.z, r1.w };

            // local (min, second-min) over my free columns, ordered-uint keys
            unsigned key1 = 0xFFFFFFFFu, key2 = 0xFFFFFFFFu;
            int k1 = 0;
#pragma unroll
            for (int k = 0; k < KC; ++k) {
                const float w = __fsub_rn(c32[k], v32[k]);
                unsigned kk = ford(w);
                if (!((mask >> k) & 1)) kk = 0xFFFFFFFFu;
                if (kk < key1) { key2 = key1; key1 = kk; k1 = k; }
                else if (kk < key2) { key2 = kk; }
            }

            // warp reduce via redux: min, owner lane, second-min, winner col
            const unsigned m1 = __reduce_min_sync(fm, key1);
            const unsigned ball = __ballot_sync(fm, key1 == m1);
            const int owner_lane = __ffs(ball) - 1;
            const unsigned cand2 = (lane == owner_lane) ? key2 : key1;
            const unsigned m2 = __reduce_min_sync(fm, cand2);
            const int col1 = __shfl_sync(fm, base + k1 + 1, owner_lane);

            if (lane == 0) {
                slots[par][wix] = ((unsigned long long)m1 << 32) | (unsigned)col1;
                m2s[par][wix] = m2;
            }
            __syncthreads();                       // the single barrier

            // slot tree: global min + global second-min key
            unsigned long long a0 = slots[par][0];
#pragma unroll
            for (int wi = 1; wi < NW; ++wi) {
                const unsigned long long x = slots[par][wi];
                if (x < a0) a0 = x;
            }
            unsigned gsec = 0xFFFFFFFFu;
#pragma unroll
            for (int wi = 0; wi < NW; ++wi) {
                const unsigned long long x = slots[par][wi];
                const unsigned cnd = (x == a0) ? m2s[par][wi] : (unsigned)(x >> 32);
                if (cnd < gsec) gsec = cnd;
            }
            par ^= 1;

            const float gw = funord((unsigned)(a0 >> 32));
            const float gs = funord(gsec);                    // NaN if none
            const bool ambig = (gs <= __fadd_rn(gw, tau));    // NaN -> false

            int jj;
            double delta_fb = 0.0;
            bool fb = false;
            if (!ambig) {
                jj = (int)(a0 & 0xffffffffu);
            } else {
                // exact fp64 among tau-window candidates via shared atomicMin
                const int fp2 = fcnt & 1;
                if (t == 0) {                      // re-arm the OTHER pair
                    fval[fp2 ^ 1] = 0xFFFFFFFFFFFFFFFFull;
                    fcol[fp2 ^ 1] = 0x7FFFFFFF;
                }
                const float thr = __fadd_rn(gw, tau);
                double lbest = DBL_MAX;
                int    lc = 0x7FFFFFFF;
#pragma unroll
                for (int k = 0; k < KC; ++k) {
                    if ((mask >> k) & 1) {
                        const float w = __fsub_rn(c32[k], v32[k]);
                        if (w <= thr) {
                            const double cur = ((double)c32[k] - ui0) - v64[k];
                            if (cur < lbest) { lbest = cur; lc = base + k + 1; }
                        }
                    }
                }
                const unsigned long long lkey = dord(lbest);
                if (lc != 0x7FFFFFFF) atomicMin(&fval[fp2], lkey);
                __syncthreads();
                const unsigned long long gkey = fval[fp2];
                if (lc != 0x7FFFFFFF && lkey == gkey) atomicMin(&fcol[fp2], lc);
                __syncthreads();
                jj = fcol[fp2];
                delta_fb = dunord(gkey);
                fb = true;
                ++fcnt;
            }

            const int pj = p[jj];

            // prefetch next chain row as early as possible
            if (pj != 0) {
                const float* nr = Cb + (size_t)(pj - 1) * QQ + base;
                r0 = *(const float4*)(nr);
                r1 = *(const float4*)(nr + 4);
            }

            // chain-sum bookkeeping: owner thread (fast) / t0 (fallback)
            if (!fb) {
                if (((jj - 1) >> 3) == t) {
                    const int kk2 = (jj - 1) & (KC - 1);
                    const double delta = ((double)c32[kk2] - ui0) - v64[kk2];
                    const double Snew = s_S + delta;
                    if (pj != 0) { ccols[len] = (short)jj; cA[len] = Snew; }
                    s_S = Snew;
                }
            } else if (t == 0) {
                const double Snew = s_S + delta_fb;
                if (pj != 0) { ccols[len] = (short)jj; cA[len] = Snew; }
                s_S = Snew;
            }

            if (((jj - 1) >> 3) == t)
                mask &= ~(1u << ((jj - 1) & (KC - 1)));

            if (pj == 0) { jsel = jj; break; }
            ++len;
            i0 = pj;
        }

        // ---- row end: apply deferred potential updates ----
        __syncthreads();
        const double S = s_S;
        if (t == 0) { u[i] += S; p[jsel] = (short)i; }
        if (t < len) { u[p[ccols[t]]] += S - cA[t]; }

        double bump = fabs(S);
        for (int c = 0; c < len; ++c) {
            const int    jc  = ccols[c];
            const double adj = S - cA[c];
            bump = fmax(bump, fabs(adj));
            const int rel = jc - 1 - base;
            if (rel >= 0 && rel < KC) {
#pragma unroll
                for (int k = 0; k < KC; ++k)
                    if (rel == k) { v64[k] -= adj; v32[k] = (float)v64[k]; }
            }
        }
        UVmax += bump;
        __syncthreads();
        if (t == 0) s_S = 0.0;
    }

    // Emit per-proposal gt index + matched mask
    for (int j = t + 1; j <= QQ; j += TLSA) {
        const int    r = p[j];
        const size_t o = (size_t)b * QQ + (j - 1);
        if (out_inds_f32) out_inds_f32[o] = (r > 0) ? (float)(r - 1) : 0.0f;
        if (out_inds_i64) out_inds_i64[o] = (r > 0) ? (long long)(r - 1) : 0LL;
        out_mask[o] = (r > 0) ? 1.0f : 0.0f;
    }
}

// ---------------------------------------------------------------------------
extern "C" void kernel_launch(void* const* d_in, const int* in_sizes, int n_in,
                              void* d_out, int out_size) {
    const float* prob    = (const float*)d_in[0];
    const float* center  = (const float*)d_in[1];
    const float* size_   = (const float*)d_in[2];
    const float* gious   = (const float*)d_in[3];
    const void*  labels  = d_in[4];
    const void*  nactual = d_in[5];

    float*     out_f32  = (float*)d_out;
    float*     inds_f32 = nullptr;
    long long* inds_i64 = nullptr;
    float*     mask;
    float*     fc;
    int i64_world = 0;

    if (out_size == 2146304) {
        i64_world = 1;
        inds_i64 = (long long*)d_out;
        mask = out_f32 + 32768;
        fc   = out_f32 + 49152;
    } else {
        inds_f32 = out_f32;
        mask = out_f32 + BB * QQ;
        fc   = out_f32 + 2 * BB * QQ;
    }

    dim3 cgrid(GG / 32, QQ / 32, BB);
    dim3 cblk(32, 8);
    cost_kernel<<<cgrid, cblk>>>(prob, center, size_, gious, labels, i64_world, fc);

    lsa_kernel<<<BB, TLSA>>>(nactual, i64_world, inds_f32, inds_i64, mask);
}